// round 11
// baseline (speedup 1.0000x reference)
#include <cuda_runtime.h>
#include <cuda_bf16.h>
#include <cstdint>
#include <math.h>

// ---------------- problem constants ----------------
#define BT    80
#define MAXN  13
#define M_DIM 1040
#define K_DIM 26400
#define N_DIM 1024
#define A_DIM 6
#define G_DIM 5

// ---------------- GEMM config (int8) ----------------
#define K_PAD2  26496             // 207 * 128
#define M_PAD2  1152              // 9 * 128
#define KC2     128               // K elems per chunk (128 int8 = 128B rows)
#define NCHUNK2 207
#define GMT     128               // m tile
#define GNT     128               // n tile
#define NSLOT   18                // x 8 n-tiles = 144 CTAs
#define STAGES  3

#define TILE_BYTES (128 * 128)           // 16KB per operand tile
#define OFF_A1 0
#define OFF_A2 (1 * TILE_BYTES)
#define OFF_B1 (2 * TILE_BYTES)
#define OFF_B2 (3 * TILE_BYTES)
#define STAGE_BYTES (4 * TILE_BYTES)     // 64KB
#define SMEM_TOTAL (STAGES * STAGE_BYTES) // 196608

// ---------------- device scratch ----------------
__device__ __align__(128) char g_Xq1[(size_t)M_PAD2 * K_PAD2];  // dense rows; unwritten = 0
__device__ __align__(128) char g_Xq2[(size_t)M_PAD2 * K_PAD2];
__device__ __align__(128) char g_Wq1[(size_t)N_DIM * K_PAD2];
__device__ __align__(128) char g_Wq2[(size_t)N_DIM * K_PAD2];
__device__ float g_Part[144 * 2 * GMT * GNT];
__device__ float g_H[(size_t)M_DIM * N_DIM];
__device__ float g_sx[M_DIM];
__device__ float g_sw[N_DIM];
__device__ int   g_swI[N_DIM];          // absmax bits (atomicMax; idempotent)
__device__ int   g_rowsrc[M_DIM];
__device__ int   g_Mvalid;

// ---------------- helpers ----------------
__device__ __forceinline__ uint32_t smem_u32(const void* p) {
    uint32_t a;
    asm("{ .reg .u64 t; cvta.to.shared.u64 t, %1; cvt.u32.u64 %0, t; }" : "=r"(a) : "l"(p));
    return a;
}
__device__ __forceinline__ void cp_async16(uint32_t dst, const void* src) {
    asm volatile("cp.async.cg.shared.global [%0], [%1], 16;" :: "r"(dst), "l"(src));
}
#define CP_COMMIT() asm volatile("cp.async.commit_group;" ::: "memory")
#define CP_WAIT1()  asm volatile("cp.async.wait_group 1;" ::: "memory")

#define LDSM_X4(r0, r1, r2, r3, addr) \
    asm volatile("ldmatrix.sync.aligned.m8n8.x4.shared.b16 {%0,%1,%2,%3}, [%4];" \
        : "=r"(r0), "=r"(r1), "=r"(r2), "=r"(r3) : "r"(addr))

__device__ __forceinline__ void mma_s8(int* c, const uint32_t* a, uint32_t b0, uint32_t b1) {
    asm volatile(
        "mma.sync.aligned.m16n8k32.row.col.s32.s8.s8.s32 "
        "{%0,%1,%2,%3}, {%4,%5,%6,%7}, {%8,%9}, {%0,%1,%2,%3};"
        : "+r"(c[0]), "+r"(c[1]), "+r"(c[2]), "+r"(c[3])
        : "r"(a[0]), "r"(a[1]), "r"(a[2]), "r"(a[3]), "r"(b0), "r"(b1));
}

__device__ __forceinline__ uint32_t swz_addr(uint32_t tile_base, int row, int c) {
    return tile_base + (uint32_t)(row * 128) + (uint32_t)((c ^ (row & 7)) << 4);
}

// 128-row x 128B int8 tile; 256 threads, 4 iters
__device__ __forceinline__ void fill_tile8(uint32_t smem_tile, const char* gbase,
                                           int row0, int k0bytes, int tid) {
    #pragma unroll
    for (int i = 0; i < 4; i++) {
        int idx = tid + i * 256;
        int row = idx >> 3;
        int c   = idx & 7;
        const char* src = gbase + (size_t)(row0 + row) * K_PAD2 + k0bytes + c * 16;
        cp_async16(swz_addr(smem_tile, row, c), src);
    }
}
__device__ __forceinline__ void fill_stage(uint32_t st, int im, int bn, int j, int tid) {
    fill_tile8(st + OFF_A1, g_Xq1, im * GMT, j * KC2, tid);
    fill_tile8(st + OFF_A2, g_Xq2, im * GMT, j * KC2, tid);
    fill_tile8(st + OFF_B1, g_Wq1, bn,       j * KC2, tid);
    fill_tile8(st + OFF_B2, g_Wq2, bn,       j * KC2, tid);
}

// ---------------- Kernel: ragged prefix / row map ----------------
__global__ __launch_bounds__(128)
void prefix_kernel(const int* __restrict__ bboxes_num) {
    __shared__ int pre[BT];
    const int tid = threadIdx.x;
    if (tid == 0) {
        int acc = 0;
        #pragma unroll 1
        for (int i = 0; i < BT; i++) {
            pre[i] = acc;
            int nv = bboxes_num[i];
            nv = nv < 1 ? 1 : (nv > MAXN ? MAXN : nv);
            acc += nv;
        }
        g_Mvalid = acc;
    }
    __syncthreads();
    for (int i = tid; i < BT; i += 128) {
        int base = pre[i];
        int nv = bboxes_num[i];
        nv = nv < 1 ? 1 : (nv > MAXN ? MAXN : nv);
        for (int n = 0; n < nv; n++) g_rowsrc[base + n] = i * MAXN + n;
    }
}

// ---------------- Kernel: W column absmax ----------------
#define WSEG 66
__global__ __launch_bounds__(256)
void wabs_kernel(const float* __restrict__ W) {
    const int n  = blockIdx.x * 256 + threadIdx.x;   // 4 blocks x
    const int k0 = blockIdx.y * (K_DIM / WSEG);      // 66 segments of 400
    float am = 0.0f;
    #pragma unroll 4
    for (int k = k0; k < k0 + (K_DIM / WSEG); k++)
        am = fmaxf(am, fabsf(W[(size_t)k * N_DIM + n]));
    atomicMax(&g_swI[n], __float_as_int(am));        // floats >= 0: int cmp ok; idempotent
}

// ---------------- Kernel: X row absmax + quantize (gathered to dense rows) ----------------
__global__ __launch_bounds__(256)
void xquant_kernel(const float* __restrict__ X) {
    const int d = blockIdx.x;
    if (d >= g_Mvalid) return;
    const int tid = threadIdx.x;
    const int src = g_rowsrc[d];
    const float4* xr = (const float4*)(X + (size_t)src * K_DIM);   // 6600 float4

    __shared__ float red[256];
    float am = 0.0f;
    for (int i = tid; i < K_DIM / 4; i += 256) {
        float4 v = xr[i];
        am = fmaxf(am, fmaxf(fmaxf(fabsf(v.x), fabsf(v.y)), fmaxf(fabsf(v.z), fabsf(v.w))));
    }
    red[tid] = am;
    __syncthreads();
    #pragma unroll
    for (int s = 128; s; s >>= 1) {
        if (tid < s) red[tid] = fmaxf(red[tid], red[tid + s]);
        __syncthreads();
    }
    const float amax = fmaxf(red[0], 1e-30f);
    const float rs = 127.0f / amax;
    if (tid == 0) g_sx[d] = amax / 127.0f;

    char* q1p = g_Xq1 + (size_t)d * K_PAD2;
    char* q2p = g_Xq2 + (size_t)d * K_PAD2;
    for (int i = tid; i < K_DIM / 4; i += 256) {
        float4 v = xr[i];
        float f[4] = {v.x, v.y, v.z, v.w};
        char c1[4], c2[4];
        #pragma unroll
        for (int p = 0; p < 4; p++) {
            float t = f[p] * rs;
            int a = __float2int_rn(t);
            int b = __float2int_rn((t - (float)a) * 254.0f);
            c1[p] = (char)a; c2[p] = (char)b;
        }
        *(char4*)(q1p + i * 4) = make_char4(c1[0], c1[1], c1[2], c1[3]);
        *(char4*)(q2p + i * 4) = make_char4(c2[0], c2[1], c2[2], c2[3]);
    }
    // K pad region [26400, 26496) never written -> static zero
}

// ---------------- Kernel: W transpose + quantize [K,N] -> [N,K_PAD2] ----------------
__global__ __launch_bounds__(256)
void wquant_kernel(const float* __restrict__ W) {
    __shared__ float s[64][33];
    const int k0 = blockIdx.x * 64;    // 413 blocks (covers to 26432; rest stays 0)
    const int n0 = blockIdx.y * 32;
    const int tid = threadIdx.x;

    {
        int kr = tid >> 2;
        int nb = (tid & 3) * 8;
        int k = k0 + kr;
        if (k < K_DIM) {
            float4 a = *(const float4*)(W + (size_t)k * N_DIM + n0 + nb);
            float4 b = *(const float4*)(W + (size_t)k * N_DIM + n0 + nb + 4);
            s[kr][nb+0]=a.x; s[kr][nb+1]=a.y; s[kr][nb+2]=a.z; s[kr][nb+3]=a.w;
            s[kr][nb+4]=b.x; s[kr][nb+5]=b.y; s[kr][nb+6]=b.z; s[kr][nb+7]=b.w;
        } else {
            #pragma unroll
            for (int i = 0; i < 8; i++) s[kr][nb+i] = 0.0f;
        }
    }
    __syncthreads();

    {
        int nr = tid >> 3;
        int kb = (tid & 7) * 8;
        int n = n0 + nr;
        float amax = fmaxf(__int_as_float(g_swI[n]), 1e-30f);
        float rsw = 127.0f / amax;
        if (blockIdx.x == 0 && kb == 0) g_sw[n] = amax / 127.0f;
        char c1[8], c2[8];
        #pragma unroll
        for (int p = 0; p < 8; p++) {
            float t = s[kb + p][nr] * rsw;
            int a = __float2int_rn(t);
            int b = __float2int_rn((t - (float)a) * 254.0f);
            c1[p] = (char)a; c2[p] = (char)b;
        }
        size_t o = (size_t)n * K_PAD2 + k0 + kb;
        *(char4*)(g_Wq1 + o)     = make_char4(c1[0], c1[1], c1[2], c1[3]);
        *(char4*)(g_Wq1 + o + 4) = make_char4(c1[4], c1[5], c1[6], c1[7]);
        *(char4*)(g_Wq2 + o)     = make_char4(c2[0], c2[1], c2[2], c2[3]);
        *(char4*)(g_Wq2 + o + 4) = make_char4(c2[4], c2[5], c2[6], c2[7]);
    }
}

// ---------------- Kernel: int8 GEMM 128x128, warp 32x64, flat partition ----------------
__global__ void __launch_bounds__(256, 1)
gemm_kernel() {
    extern __shared__ char smem[];
    const uint32_t sb = smem_u32(smem);
    const int tid  = threadIdx.x;
    const int lane = tid & 31;
    const int wid  = tid >> 5;
    const int bid  = blockIdx.x;
    const int in   = bid & 7;
    const int slot = bid >> 3;
    const int bn   = in * GNT;

    const int mv     = g_Mvalid;
    const int tilesM = (mv + GMT - 1) / GMT;
    const int totalF = tilesM * NCHUNK2;
    const int f0 = (slot * totalF) / NSLOT;
    const int f1 = ((slot + 1) * totalF) / NSLOT;

    const int m_off = (wid & 3) * 32;     // 4 warps down M
    const int n_off = (wid >> 2) * 64;    // 2 warps across N

    int acc1[2][8][4], acc23[2][8][4];
    #pragma unroll
    for (int mi = 0; mi < 2; mi++)
        #pragma unroll
        for (int ni = 0; ni < 8; ni++)
            #pragma unroll
            for (int q = 0; q < 4; q++) { acc1[mi][ni][q] = 0; acc23[mi][ni][q] = 0; }

    // s8 fragment addressing (A and B identical): row = base + (lane&15), 16B-col = lane>>4
    const int rA = lane & 15;
    const int c16 = lane >> 4;

    int im = f0 / NCHUNK2;
    int j  = f0 - im * NCHUNK2;

    fill_stage(sb + 0 * STAGE_BYTES, im, bn, j, tid);
    CP_COMMIT();
    if (f0 + 1 < f1) {
        int im1 = (f0 + 1) / NCHUNK2;
        int j1  = (f0 + 1) - im1 * NCHUNK2;
        fill_stage(sb + 1 * STAGE_BYTES, im1, bn, j1, tid);
    }
    CP_COMMIT();

    int seg = 0;
    for (int f = f0; f < f1; f++) {
        const int sidx = (f - f0) % STAGES;
        CP_WAIT1();
        __syncthreads();

        if (f + 2 < f1) {
            int imp = (f + 2) / NCHUNK2;
            int jp  = (f + 2) - imp * NCHUNK2;
            fill_stage(sb + ((f - f0 + 2) % STAGES) * STAGE_BYTES, imp, bn, jp, tid);
        }
        CP_COMMIT();

        const uint32_t st = sb + sidx * STAGE_BYTES;
        #pragma unroll
        for (int kk = 0; kk < 4; kk++) {            // 4 k32 steps per 128-elem chunk
            uint32_t a1[2][4], a2[2][4], b1[4][4], b2[4][4];
            #pragma unroll
            for (int mi = 0; mi < 2; mi++) {
                LDSM_X4(a1[mi][0], a1[mi][1], a1[mi][2], a1[mi][3],
                        swz_addr(st + OFF_A1, m_off + mi * 16 + rA, kk * 2 + c16));
                LDSM_X4(a2[mi][0], a2[mi][1], a2[mi][2], a2[mi][3],
                        swz_addr(st + OFF_A2, m_off + mi * 16 + rA, kk * 2 + c16));
            }
            #pragma unroll
            for (int nb = 0; nb < 4; nb++) {
                LDSM_X4(b1[nb][0], b1[nb][1], b1[nb][2], b1[nb][3],
                        swz_addr(st + OFF_B1, n_off + nb * 16 + rA, kk * 2 + c16));
                LDSM_X4(b2[nb][0], b2[nb][1], b2[nb][2], b2[nb][3],
                        swz_addr(st + OFF_B2, n_off + nb * 16 + rA, kk * 2 + c16));
            }
            #pragma unroll
            for (int mi = 0; mi < 2; mi++) {
                #pragma unroll
                for (int ni = 0; ni < 8; ni++) {
                    const int nb = ni >> 1, sub = ni & 1;
                    mma_s8(acc1[mi][ni],  a1[mi], b1[nb][sub], b1[nb][sub + 2]);  // q1*p1
                    mma_s8(acc23[mi][ni], a1[mi], b2[nb][sub], b2[nb][sub + 2]);  // q1*p2
                    mma_s8(acc23[mi][ni], a2[mi], b1[nb][sub], b1[nb][sub + 2]);  // q2*p1
                }
            }
        }

        // advance / flush at m-tile boundary or range end
        j++;
        const bool bound = (j == NCHUNK2);
        const bool last  = (f == f1 - 1);
        if (bound) j = 0;
        if (bound || last) {
            float* P = g_Part + ((size_t)bid * 2 + seg) * (GMT * GNT);
            #pragma unroll
            for (int mi = 0; mi < 2; mi++) {
                #pragma unroll
                for (int ni = 0; ni < 8; ni++) {
                    int r0 = m_off + mi * 16 + (lane >> 2);
                    int cc = n_off + ni * 8 + (lane & 3) * 2;
                    float v0 = (float)acc1[mi][ni][0] + (float)acc23[mi][ni][0] * (1.0f/254.0f);
                    float v1 = (float)acc1[mi][ni][1] + (float)acc23[mi][ni][1] * (1.0f/254.0f);
                    float v2 = (float)acc1[mi][ni][2] + (float)acc23[mi][ni][2] * (1.0f/254.0f);
                    float v3 = (float)acc1[mi][ni][3] + (float)acc23[mi][ni][3] * (1.0f/254.0f);
                    *(float2*)(P + r0 * GNT + cc)       = make_float2(v0, v1);
                    *(float2*)(P + (r0 + 8) * GNT + cc) = make_float2(v2, v3);
                    #pragma unroll
                    for (int q = 0; q < 4; q++) { acc1[mi][ni][q] = 0; acc23[mi][ni][q] = 0; }
                }
            }
            seg++;
            if (bound) im++;
        }
    }
}

// ---------------- Kernel: gather partials + scales + bias + ReLU + scatter ----------------
__global__ __launch_bounds__(256)
void reduce_kernel(const float* __restrict__ bias) {
    const int idx = blockIdx.x * 256 + threadIdx.x;  // float4 index over [M_DIM, 256]
    const int d   = idx >> 8;
    const int mv  = g_Mvalid;
    if (d >= mv) return;
    const int c    = idx & 255;
    const int im   = d >> 7;
    const int rloc = d & 127;
    const int in   = c >> 5;
    const int lc   = (c & 31) * 4;

    const int tilesM = (mv + GMT - 1) / GMT;
    const int totalF = tilesM * NCHUNK2;

    int sLo = (int)(((long)im * NCHUNK2 * NSLOT) / totalF) - 1;
    if (sLo < 0) sLo = 0;
    int sHi = (int)(((long)(im + 1) * NCHUNK2 * NSLOT) / totalF) + 2;
    if (sHi > NSLOT) sHi = NSLOT;

    float4 sum = make_float4(0.f, 0.f, 0.f, 0.f);
    #pragma unroll 1
    for (int slot = sLo; slot < sHi; slot++) {
        int f0   = (slot * totalF) / NSLOT;
        int f1   = ((slot + 1) * totalF) / NSLOT;
        int imLo = f0 / NCHUNK2;
        int imHi = (f1 - 1) / NCHUNK2;
        int seg = -1;
        if (im == imLo) seg = 0;
        else if (im == imHi) seg = 1;
        if (seg >= 0) {
            const float* P = g_Part + (((size_t)(slot * 8 + in)) * 2 + seg) * (GMT * GNT);
            float4 v = *(const float4*)(P + rloc * GNT + lc);
            sum.x += v.x; sum.y += v.y; sum.z += v.z; sum.w += v.w;
        }
    }
    const float sx = g_sx[d];
    const float4 sw = *(const float4*)(g_sw + c * 4);
    const float4 bi = *(const float4*)(bias + c * 4);
    float4 o;
    o.x = fmaxf(sum.x * sx * sw.x + bi.x, 0.0f);
    o.y = fmaxf(sum.y * sx * sw.y + bi.y, 0.0f);
    o.z = fmaxf(sum.z * sx * sw.z + bi.z, 0.0f);
    o.w = fmaxf(sum.w * sx * sw.w + bi.w, 0.0f);
    int row = g_rowsrc[d];
    *(float4*)(g_H + (size_t)row * N_DIM + c * 4) = o;
}

// ---------------- Kernel: merged head (y==0: pool+activities, y>=1: actions row y-1) ----------------
__global__ __launch_bounds__(256)
void head_kernel(const float* __restrict__ w_act,
                 const float* __restrict__ b_act,
                 const float* __restrict__ w_acty,
                 const float* __restrict__ b_acty,
                 const int*   __restrict__ bboxes_num,
                 float* __restrict__ out) {
    const int bt   = blockIdx.x;
    const int mode = blockIdx.y;
    const int tid  = threadIdx.x;
    const int lane = tid & 31;
    const int warp = tid >> 5;

    int nvalid = bboxes_num[bt];
    nvalid = nvalid < 1 ? 1 : (nvalid > MAXN ? MAXN : nvalid);

    if (mode == 0) {
        const float4* h4 = (const float4*)(g_H + (size_t)bt * MAXN * N_DIM);
        __shared__ float pooled[N_DIM];
        {
            float4 m = h4[tid];
            #pragma unroll
            for (int n = 1; n < MAXN; n++) {
                if (n < nvalid) {
                    float4 v = h4[n * 256 + tid];
                    m.x = fmaxf(m.x, v.x); m.y = fmaxf(m.y, v.y);
                    m.z = fmaxf(m.z, v.z); m.w = fmaxf(m.w, v.w);
                }
            }
            ((float4*)pooled)[tid] = m;
        }
        __syncthreads();
        for (int g = warp; g < G_DIM; g += 8) {
            float s = 0.0f;
            for (int i = lane; i < 256; i += 32) {
                float4 pv = ((const float4*)pooled)[i];
                int f = i * 4;
                s = fmaf(pv.x, w_acty[(f + 0) * G_DIM + g], s);
                s = fmaf(pv.y, w_acty[(f + 1) * G_DIM + g], s);
                s = fmaf(pv.z, w_acty[(f + 2) * G_DIM + g], s);
                s = fmaf(pv.w, w_acty[(f + 3) * G_DIM + g], s);
            }
            #pragma unroll
            for (int o = 16; o; o >>= 1) s += __shfl_xor_sync(0xFFFFFFFFu, s, o);
            if (lane == 0)
                out[BT * MAXN * A_DIM + bt * G_DIM + g] = s + b_acty[g];
        }
    } else {
        const int n = mode - 1;
        if (warp >= A_DIM) return;
        const int a = warp;
        if (n >= nvalid) {
            if (lane == 0) out[(bt * MAXN + n) * A_DIM + a] = 0.0f;
            return;
        }
        const float4* hr = (const float4*)(g_H + ((size_t)bt * MAXN + n) * N_DIM);
        float s = 0.0f;
        #pragma unroll
        for (int r = 0; r < 8; r++) {
            int i = lane + r * 32;
            float4 hv = hr[i];
            int f = i * 4;
            s = fmaf(hv.x, w_act[(f + 0) * A_DIM + a], s);
            s = fmaf(hv.y, w_act[(f + 1) * A_DIM + a], s);
            s = fmaf(hv.z, w_act[(f + 2) * A_DIM + a], s);
            s = fmaf(hv.w, w_act[(f + 3) * A_DIM + a], s);
        }
        #pragma unroll
        for (int o = 16; o; o >>= 1) s += __shfl_xor_sync(0xFFFFFFFFu, s, o);
        if (lane == 0) out[(bt * MAXN + n) * A_DIM + a] = s + b_act[a];
    }
}

// ---------------- launch ----------------
extern "C" void kernel_launch(void* const* d_in, const int* in_sizes, int n_in,
                              void* d_out, int out_size) {
    const float* X      = (const float*)d_in[0];
    const float* w_emb  = (const float*)d_in[1];
    const float* b_emb  = (const float*)d_in[2];
    const float* w_act  = (const float*)d_in[3];
    const float* b_act  = (const float*)d_in[4];
    const float* w_acty = (const float*)d_in[5];
    const float* b_acty = (const float*)d_in[6];
    const int*   bboxes = (const int*)d_in[7];
    float* out = (float*)d_out;

    cudaFuncSetAttribute(gemm_kernel, cudaFuncAttributeMaxDynamicSharedMemorySize, SMEM_TOTAL);

    prefix_kernel<<<1, 128>>>(bboxes);
    {
        dim3 g(N_DIM / 256, WSEG);           // 4 x 66
        wabs_kernel<<<g, 256>>>(w_emb);
    }
    xquant_kernel<<<M_DIM, 256>>>(X);        // guard d < mv inside
    {
        dim3 g(413, N_DIM / 32);             // transpose + quantize W
        wquant_kernel<<<g, 256>>>(w_emb);
    }
    gemm_kernel<<<8 * NSLOT, 256, SMEM_TOTAL>>>();   // 144 CTAs, flat-balanced
    {
        int blocks = (M_DIM * 256 + 255) / 256;
        reduce_kernel<<<blocks, 256>>>(b_emb);
    }
    {
        dim3 g(BT, MAXN + 1);
        head_kernel<<<g, 256>>>(w_act, b_act, w_acty, b_acty, bboxes, out);
    }
}

// round 12
// speedup vs baseline: 2.7418x; 2.7418x over previous
#include <cuda_runtime.h>
#include <cuda_bf16.h>
#include <cstdint>
#include <math.h>

// ---------------- problem constants ----------------
#define BT    80
#define MAXN  13
#define M_DIM 1040
#define K_DIM 26400
#define N_DIM 1024
#define A_DIM 6
#define G_DIM 5

// ---------------- GEMM config ----------------
#define K_PAD  26432              // 413 * 64
#define M_PAD  1152               // 9 * 128
#define KC     64                 // K elems per chunk (128B rows)
#define NCHUNK (K_PAD / KC)       // 413
#define GMT    128                // m tile
#define GNT    128                // n tile
#define NSLOT  18                 // flat-range slots (x8 n-tiles = 144 CTAs)
#define STAGES 3

#define TILE_BYTES (128 * 128)           // 16KB per operand tile
#define OFF_AH 0
#define OFF_AL (1 * TILE_BYTES)
#define OFF_BH (2 * TILE_BYTES)
#define OFF_BL (3 * TILE_BYTES)
#define STAGE_BYTES (4 * TILE_BYTES)     // 64KB
#define SMEM_TOTAL (STAGES * STAGE_BYTES) // 196608, 1 CTA/SM

#define XBLOCKS ((M_DIM * (K_DIM / 4) + 255) / 256)   // 26813
#define WBLOCKS ((K_PAD / 64) * (N_DIM / 32))          // 13216

// ---------------- device scratch ----------------
__device__ __align__(128) __nv_bfloat16 g_Xh[(size_t)M_PAD * K_PAD];  // dense rows
__device__ __align__(128) __nv_bfloat16 g_Xl[(size_t)M_PAD * K_PAD];
__device__ __align__(128) __nv_bfloat16 g_Wh[(size_t)N_DIM * K_PAD];
__device__ __align__(128) __nv_bfloat16 g_Wl[(size_t)N_DIM * K_PAD];
__device__ float g_Part[144 * 2 * GMT * GNT];   // per-CTA partial segments
__device__ float g_H[(size_t)M_DIM * N_DIM];
__device__ int   g_rowsrc[M_DIM];
__device__ int   g_Mvalid;

// ---------------- helpers ----------------
__device__ __forceinline__ uint32_t smem_u32(const void* p) {
    uint32_t a;
    asm("{ .reg .u64 t; cvta.to.shared.u64 t, %1; cvt.u32.u64 %0, t; }" : "=r"(a) : "l"(p));
    return a;
}
__device__ __forceinline__ void cp_async16(uint32_t dst, const void* src) {
    asm volatile("cp.async.cg.shared.global [%0], [%1], 16;" :: "r"(dst), "l"(src));
}
#define CP_COMMIT() asm volatile("cp.async.commit_group;" ::: "memory")
#define CP_WAIT1()  asm volatile("cp.async.wait_group 1;" ::: "memory")

#define LDSM_X4(r0, r1, r2, r3, addr) \
    asm volatile("ldmatrix.sync.aligned.m8n8.x4.shared.b16 {%0,%1,%2,%3}, [%4];" \
        : "=r"(r0), "=r"(r1), "=r"(r2), "=r"(r3) : "r"(addr))

__device__ __forceinline__ void mma_bf16(float* c, const uint32_t* a, const uint32_t* b) {
    asm volatile(
        "mma.sync.aligned.m16n8k16.row.col.f32.bf16.bf16.f32 "
        "{%0,%1,%2,%3}, {%4,%5,%6,%7}, {%8,%9}, {%0,%1,%2,%3};"
        : "+f"(c[0]), "+f"(c[1]), "+f"(c[2]), "+f"(c[3])
        : "r"(a[0]), "r"(a[1]), "r"(a[2]), "r"(a[3]), "r"(b[0]), "r"(b[1]));
}

__device__ __forceinline__ uint32_t swz_addr(uint32_t tile_base, int row, int c) {
    return tile_base + (uint32_t)(row * 128) + (uint32_t)((c ^ (row & 7)) << 4);
}

// 128-row tile: 1024 chunks / 256 threads = 4 iters
__device__ __forceinline__ void fill_tile128(uint32_t smem_tile, const __nv_bfloat16* gbase,
                                             int row0, int k0, int tid) {
    const char* base = (const char*)gbase;
    #pragma unroll
    for (int i = 0; i < 4; i++) {
        int idx = tid + i * 256;
        int row = idx >> 3;
        int c   = idx & 7;
        const char* src = base + ((size_t)(row0 + row) * K_PAD + (size_t)k0) * 2 + c * 16;
        cp_async16(swz_addr(smem_tile, row, c), src);
    }
}
__device__ __forceinline__ void fill_stage(uint32_t st, int im, int bn, int j, int tid) {
    fill_tile128(st + OFF_AH, g_Xh, im * GMT, j * KC, tid);
    fill_tile128(st + OFF_AL, g_Xl, im * GMT, j * KC, tid);
    fill_tile128(st + OFF_BH, g_Wh, bn,       j * KC, tid);
    fill_tile128(st + OFF_BL, g_Wl, bn,       j * KC, tid);
}

// load all fragments for one kk step
__device__ __forceinline__ void load_frags(uint32_t st, int kk, int aRow0, int cA,
                                           int bRow0, int cB,
                                           uint32_t ah[2][4], uint32_t al[2][4],
                                           uint32_t bh[4][4], uint32_t bl[4][4]) {
    #pragma unroll
    for (int mi = 0; mi < 2; mi++) {
        LDSM_X4(ah[mi][0], ah[mi][1], ah[mi][2], ah[mi][3],
                swz_addr(st + OFF_AH, aRow0 + mi * 16, kk * 2 + cA));
        LDSM_X4(al[mi][0], al[mi][1], al[mi][2], al[mi][3],
                swz_addr(st + OFF_AL, aRow0 + mi * 16, kk * 2 + cA));
    }
    #pragma unroll
    for (int nb = 0; nb < 4; nb++) {
        LDSM_X4(bh[nb][0], bh[nb][1], bh[nb][2], bh[nb][3],
                swz_addr(st + OFF_BH, bRow0 + nb * 16, kk * 2 + cB));
        LDSM_X4(bl[nb][0], bl[nb][1], bl[nb][2], bl[nb][3],
                swz_addr(st + OFF_BL, bRow0 + nb * 16, kk * 2 + cB));
    }
}

// ---------------- Kernel: ragged prefix / row map ----------------
__global__ __launch_bounds__(128)
void prefix_kernel(const int* __restrict__ bboxes_num) {
    __shared__ int pre[BT];
    const int tid = threadIdx.x;
    if (tid == 0) {
        int acc = 0;
        #pragma unroll 1
        for (int i = 0; i < BT; i++) {
            pre[i] = acc;
            int nv = bboxes_num[i];
            nv = nv < 1 ? 1 : (nv > MAXN ? MAXN : nv);
            acc += nv;
        }
        g_Mvalid = acc;
    }
    __syncthreads();
    for (int i = tid; i < BT; i += 128) {
        int base = pre[i];
        int nv = bboxes_num[i];
        nv = nv < 1 ? 1 : (nv > MAXN ? MAXN : nv);
        for (int n = 0; n < nv; n++) g_rowsrc[base + n] = i * MAXN + n;
    }
}

// ---------------- Kernel: merged converts (X gather-split | W transpose-split) ----------------
__global__ __launch_bounds__(256)
void convert_kernel(const float* __restrict__ X, const float* __restrict__ W) {
    __shared__ float s[64][33];
    const int bid = blockIdx.x;
    const int tid = threadIdx.x;

    if (bid < XBLOCKS) {
        size_t t = (size_t)bid * 256 + tid;
        const size_t total = (size_t)M_DIM * (K_DIM / 4);
        if (t >= total) return;
        int d  = (int)(t / (K_DIM / 4));
        if (d >= g_Mvalid) return;
        int kk = (int)(t % (K_DIM / 4)) * 4;
        int src = g_rowsrc[d];
        float4 v = *(const float4*)(X + (size_t)src * K_DIM + kk);
        float f[4] = {v.x, v.y, v.z, v.w};
        uint32_t hi[2], lo[2];
        #pragma unroll
        for (int p = 0; p < 2; p++) {
            __nv_bfloat16 h0 = __float2bfloat16(f[2*p+0]);
            __nv_bfloat16 h1 = __float2bfloat16(f[2*p+1]);
            __nv_bfloat16 l0 = __float2bfloat16(f[2*p+0] - __bfloat162float(h0));
            __nv_bfloat16 l1 = __float2bfloat16(f[2*p+1] - __bfloat162float(h1));
            hi[p] = (uint32_t)__bfloat16_as_ushort(h0) | ((uint32_t)__bfloat16_as_ushort(h1) << 16);
            lo[p] = (uint32_t)__bfloat16_as_ushort(l0) | ((uint32_t)__bfloat16_as_ushort(l1) << 16);
        }
        size_t o = (size_t)d * K_PAD + kk;
        *(uint2*)(g_Xh + o) = make_uint2(hi[0], hi[1]);
        *(uint2*)(g_Xl + o) = make_uint2(lo[0], lo[1]);
    } else {
        const int wb = bid - XBLOCKS;
        const int k0 = (wb % (K_PAD / 64)) * 64;
        const int n0 = (wb / (K_PAD / 64)) * 32;
        {
            int kr = tid >> 2;
            int nb = (tid & 3) * 8;
            int k = k0 + kr;
            if (k < K_DIM) {
                float4 a = *(const float4*)(W + (size_t)k * N_DIM + n0 + nb);
                float4 b = *(const float4*)(W + (size_t)k * N_DIM + n0 + nb + 4);
                s[kr][nb+0]=a.x; s[kr][nb+1]=a.y; s[kr][nb+2]=a.z; s[kr][nb+3]=a.w;
                s[kr][nb+4]=b.x; s[kr][nb+5]=b.y; s[kr][nb+6]=b.z; s[kr][nb+7]=b.w;
            } else {
                #pragma unroll
                for (int i = 0; i < 8; i++) s[kr][nb+i] = 0.0f;
            }
        }
        __syncthreads();
        {
            int nr = tid >> 3;
            int kb = (tid & 7) * 8;
            uint32_t hi[4], lo[4];
            #pragma unroll
            for (int p = 0; p < 4; p++) {
                float f0 = s[kb + 2*p + 0][nr];
                float f1 = s[kb + 2*p + 1][nr];
                __nv_bfloat16 h0 = __float2bfloat16(f0);
                __nv_bfloat16 h1 = __float2bfloat16(f1);
                __nv_bfloat16 l0 = __float2bfloat16(f0 - __bfloat162float(h0));
                __nv_bfloat16 l1 = __float2bfloat16(f1 - __bfloat162float(h1));
                hi[p] = (uint32_t)__bfloat16_as_ushort(h0) | ((uint32_t)__bfloat16_as_ushort(h1) << 16);
                lo[p] = (uint32_t)__bfloat16_as_ushort(l0) | ((uint32_t)__bfloat16_as_ushort(l1) << 16);
            }
            size_t o = (size_t)(n0 + nr) * K_PAD + k0 + kb;
            *(uint4*)(g_Wh + o) = make_uint4(hi[0], hi[1], hi[2], hi[3]);
            *(uint4*)(g_Wl + o) = make_uint4(lo[0], lo[1], lo[2], lo[3]);
        }
    }
}

// ---------------- Kernel: GEMM 128x128, warp 32x64, flat partition, frag double-buffer ----------------
__global__ void __launch_bounds__(256, 1)
gemm_kernel() {
    extern __shared__ char smem[];
    const uint32_t sb = smem_u32(smem);
    const int tid  = threadIdx.x;
    const int lane = tid & 31;
    const int wid  = tid >> 5;
    const int bid  = blockIdx.x;
    const int in   = bid & 7;
    const int slot = bid >> 3;
    const int bn   = in * GNT;

    const int mv     = g_Mvalid;
    const int tilesM = (mv + GMT - 1) / GMT;
    const int totalF = tilesM * NCHUNK;
    const int f0 = (slot * totalF) / NSLOT;
    const int f1 = ((slot + 1) * totalF) / NSLOT;

    const int m_off = (wid & 3) * 32;     // 4 warps down M
    const int n_off = (wid >> 2) * 64;    // 2 warps across N

    float acc[2][8][4];
    #pragma unroll
    for (int mi = 0; mi < 2; mi++)
        #pragma unroll
        for (int ni = 0; ni < 8; ni++)
            #pragma unroll
            for (int q = 0; q < 4; q++) acc[mi][ni][q] = 0.0f;

    const int aRow0 = m_off + (lane & 15);
    const int cA    = lane >> 4;
    const int bRow0 = n_off + ((lane & 16) >> 1) + (lane & 7);
    const int cB    = (lane >> 3) & 1;

    int im = f0 / NCHUNK;
    int j  = f0 - im * NCHUNK;

    fill_stage(sb + 0 * STAGE_BYTES, im, bn, j, tid);
    CP_COMMIT();
    if (f0 + 1 < f1) {
        int im1 = (f0 + 1) / NCHUNK;
        int j1  = (f0 + 1) - im1 * NCHUNK;
        fill_stage(sb + 1 * STAGE_BYTES, im1, bn, j1, tid);
    }
    CP_COMMIT();

    int seg = 0;
    for (int f = f0; f < f1; f++) {
        const int sidx = (f - f0) % STAGES;
        CP_WAIT1();
        __syncthreads();

        if (f + 2 < f1) {
            int imp = (f + 2) / NCHUNK;
            int jp  = (f + 2) - imp * NCHUNK;
            fill_stage(sb + ((f - f0 + 2) % STAGES) * STAGE_BYTES, imp, bn, jp, tid);
        }
        CP_COMMIT();

        const uint32_t st = sb + sidx * STAGE_BYTES;

        // double-buffered fragments across kk
        uint32_t ah[2][2][4], al[2][2][4], bh[2][4][4], bl[2][4][4];
        load_frags(st, 0, aRow0, cA, bRow0, cB, ah[0], al[0], bh[0], bl[0]);
        #pragma unroll
        for (int kk = 0; kk < 4; kk++) {
            const int cur = kk & 1;
            const int nxt = cur ^ 1;
            if (kk < 3)
                load_frags(st, kk + 1, aRow0, cA, bRow0, cB, ah[nxt], al[nxt], bh[nxt], bl[nxt]);
            #pragma unroll
            for (int mi = 0; mi < 2; mi++) {
                #pragma unroll
                for (int ni = 0; ni < 8; ni++) {
                    const uint32_t* fh = &bh[cur][ni >> 1][(ni & 1) * 2];
                    const uint32_t* fl = &bl[cur][ni >> 1][(ni & 1) * 2];
                    mma_bf16(acc[mi][ni], ah[cur][mi], fh);
                    mma_bf16(acc[mi][ni], ah[cur][mi], fl);
                    mma_bf16(acc[mi][ni], al[cur][mi], fh);
                }
            }
        }

        // advance / flush at m-tile boundary or range end
        j++;
        const bool bound = (j == NCHUNK);
        const bool last  = (f == f1 - 1);
        if (bound) j = 0;
        if (bound || last) {
            float* P = g_Part + ((size_t)bid * 2 + seg) * (GMT * GNT);
            #pragma unroll
            for (int mi = 0; mi < 2; mi++) {
                #pragma unroll
                for (int ni = 0; ni < 8; ni++) {
                    int r0 = m_off + mi * 16 + (lane >> 2);
                    int cc = n_off + ni * 8 + (lane & 3) * 2;
                    *(float2*)(P + r0 * GNT + cc) = make_float2(acc[mi][ni][0], acc[mi][ni][1]);
                    *(float2*)(P + (r0 + 8) * GNT + cc) = make_float2(acc[mi][ni][2], acc[mi][ni][3]);
                    #pragma unroll
                    for (int q = 0; q < 4; q++) acc[mi][ni][q] = 0.0f;
                }
            }
            seg++;
            if (bound) im++;
        }
    }
}

// ---------------- Kernel: gather partials + bias + ReLU + scatter to g_H ----------------
__global__ __launch_bounds__(256)
void reduce_kernel(const float* __restrict__ bias) {
    const int idx = blockIdx.x * 256 + threadIdx.x;  // float4 index over [M_DIM, 256]
    const int d   = idx >> 8;
    const int mv  = g_Mvalid;
    if (d >= mv) return;
    const int c    = idx & 255;
    const int im   = d >> 7;                         // m-tile (128 rows)
    const int rloc = d & 127;
    const int in   = c >> 5;
    const int lc   = (c & 31) * 4;

    const int tilesM = (mv + GMT - 1) / GMT;
    const int totalF = tilesM * NCHUNK;

    // slots whose flat range can intersect m-tile im (body re-validates)
    int sLo = (int)(((long)im * NCHUNK * NSLOT) / totalF) - 1;
    if (sLo < 0) sLo = 0;
    int sHi = (int)(((long)(im + 1) * NCHUNK * NSLOT) / totalF) + 2;
    if (sHi > NSLOT) sHi = NSLOT;

    float4 sum = *(const float4*)(bias + c * 4);
    #pragma unroll 1
    for (int slot = sLo; slot < sHi; slot++) {
        int f0   = (slot * totalF) / NSLOT;
        int f1   = ((slot + 1) * totalF) / NSLOT;
        int imLo = f0 / NCHUNK;
        int imHi = (f1 - 1) / NCHUNK;
        int seg = -1;
        if (im == imLo) seg = 0;
        else if (im == imHi) seg = 1;
        if (seg >= 0) {
            const float* P = g_Part + (((size_t)(slot * 8 + in)) * 2 + seg) * (GMT * GNT);
            float4 v = *(const float4*)(P + rloc * GNT + lc);
            sum.x += v.x; sum.y += v.y; sum.z += v.z; sum.w += v.w;
        }
    }
    float4 o;
    o.x = fmaxf(sum.x, 0.0f);
    o.y = fmaxf(sum.y, 0.0f);
    o.z = fmaxf(sum.z, 0.0f);
    o.w = fmaxf(sum.w, 0.0f);
    int row = g_rowsrc[d];
    *(float4*)(g_H + (size_t)row * N_DIM + c * 4) = o;
}

// ---------------- Kernel: merged head (y==0: pool+activities, y>=1: actions row y-1) ----------------
__global__ __launch_bounds__(256)
void head_kernel(const float* __restrict__ w_act,
                 const float* __restrict__ b_act,
                 const float* __restrict__ w_acty,
                 const float* __restrict__ b_acty,
                 const int*   __restrict__ bboxes_num,
                 float* __restrict__ out) {
    const int bt   = blockIdx.x;
    const int mode = blockIdx.y;
    const int tid  = threadIdx.x;
    const int lane = tid & 31;
    const int warp = tid >> 5;

    int nvalid = bboxes_num[bt];
    nvalid = nvalid < 1 ? 1 : (nvalid > MAXN ? MAXN : nvalid);

    if (mode == 0) {
        const float4* h4 = (const float4*)(g_H + (size_t)bt * MAXN * N_DIM);
        __shared__ float pooled[N_DIM];
        {
            float4 m = h4[tid];
            #pragma unroll
            for (int n = 1; n < MAXN; n++) {
                if (n < nvalid) {
                    float4 v = h4[n * 256 + tid];
                    m.x = fmaxf(m.x, v.x); m.y = fmaxf(m.y, v.y);
                    m.z = fmaxf(m.z, v.z); m.w = fmaxf(m.w, v.w);
                }
            }
            ((float4*)pooled)[tid] = m;
        }
        __syncthreads();
        for (int g = warp; g < G_DIM; g += 8) {
            float s = 0.0f;
            for (int i = lane; i < 256; i += 32) {
                float4 pv = ((const float4*)pooled)[i];
                int f = i * 4;
                s = fmaf(pv.x, w_acty[(f + 0) * G_DIM + g], s);
                s = fmaf(pv.y, w_acty[(f + 1) * G_DIM + g], s);
                s = fmaf(pv.z, w_acty[(f + 2) * G_DIM + g], s);
                s = fmaf(pv.w, w_acty[(f + 3) * G_DIM + g], s);
            }
            #pragma unroll
            for (int o = 16; o; o >>= 1) s += __shfl_xor_sync(0xFFFFFFFFu, s, o);
            if (lane == 0)
                out[BT * MAXN * A_DIM + bt * G_DIM + g] = s + b_acty[g];
        }
    } else {
        const int n = mode - 1;
        if (warp >= A_DIM) return;
        const int a = warp;
        if (n >= nvalid) {
            if (lane == 0) out[(bt * MAXN + n) * A_DIM + a] = 0.0f;
            return;
        }
        const float4* hr = (const float4*)(g_H + ((size_t)bt * MAXN + n) * N_DIM);
        float s = 0.0f;
        #pragma unroll
        for (int r = 0; r < 8; r++) {
            int i = lane + r * 32;
            float4 hv = hr[i];
            int f = i * 4;
            s = fmaf(hv.x, w_act[(f + 0) * A_DIM + a], s);
            s = fmaf(hv.y, w_act[(f + 1) * A_DIM + a], s);
            s = fmaf(hv.z, w_act[(f + 2) * A_DIM + a], s);
            s = fmaf(hv.w, w_act[(f + 3) * A_DIM + a], s);
        }
        #pragma unroll
        for (int o = 16; o; o >>= 1) s += __shfl_xor_sync(0xFFFFFFFFu, s, o);
        if (lane == 0) out[(bt * MAXN + n) * A_DIM + a] = s + b_act[a];
    }
}

// ---------------- launch ----------------
extern "C" void kernel_launch(void* const* d_in, const int* in_sizes, int n_in,
                              void* d_out, int out_size) {
    const float* X      = (const float*)d_in[0];
    const float* w_emb  = (const float*)d_in[1];
    const float* b_emb  = (const float*)d_in[2];
    const float* w_act  = (const float*)d_in[3];
    const float* b_act  = (const float*)d_in[4];
    const float* w_acty = (const float*)d_in[5];
    const float* b_acty = (const float*)d_in[6];
    const int*   bboxes = (const int*)d_in[7];
    float* out = (float*)d_out;

    cudaFuncSetAttribute(gemm_kernel, cudaFuncAttributeMaxDynamicSharedMemorySize, SMEM_TOTAL);

    prefix_kernel<<<1, 128>>>(bboxes);
    convert_kernel<<<XBLOCKS + WBLOCKS, 256>>>(X, w_emb);
    gemm_kernel<<<8 * NSLOT, 256, SMEM_TOTAL>>>();       // 144 CTAs, flat-balanced
    {
        int blocks = (M_DIM * 256 + 255) / 256;
        reduce_kernel<<<blocks, 256>>>(b_emb);
    }
    {
        dim3 g(BT, MAXN + 1);
        head_kernel<<<g, 256>>>(w_act, b_act, w_acty, b_acty, bboxes, out);
    }
}